// round 15
// baseline (speedup 1.0000x reference)
#include <cuda_runtime.h>

typedef unsigned long long ull;

#define Lg 64
#define Bg 1024
#define TH 16
#define NTILES (Lg/TH)          // 4
#define THREADS 512
#define R1 (TH+4)               // 20 conv1 output rows (halo 2)
#define R2 (TH+2)               // 18 conv2 output rows (halo 1)
#define RZ (TH+6)               // 22 input rows (halo 3)
#define PW 40                   // pairs per row padded: entries 0..39, pair p at p+1
                                // (row stride 40 ull = 16 banks -> 2-rows-per-warp
                                //  act loads are bank-conflict-free)

// ---- shared memory layout (ull units) ----
#define S1U 0                               // 16*20*40 = 12800
#define S2U (S1U + 16*R1*PW)                // 12800 (+16*18*40 = 11520)
#define SZU (S2U + 16*R2*PW)                // 24320 (+22*40 = 880)
#define WS1 (SZU + RZ*PW)                   // 25200: W1 scalar floats (1152 ull)
#define WS0 (WS1 + 1152)                    // 26352: W0 scalar (72 ull)
#define WU2 (WS0 + 72)                      // 26424: W2 packed pairs (144 ull)
#define BFU (WU2 + 144)                     // 26568: packed biases (33 ull)
#define U_TOTAL (BFU + 33)                  // 26601
#define SMEM_BYTES ((size_t)U_TOTAL * 8)    // 212808 B (<= 227KB cap)

// ---- packed f32x2 helpers (sm_100+) : per-lane exact fp32 ops ----
__device__ __forceinline__ ull pk(float lo, float hi) {
    ull r; asm("mov.b64 %0, {%1, %2};" : "=l"(r) : "f"(lo), "f"(hi)); return r;
}
__device__ __forceinline__ void upk(ull v, float& lo, float& hi) {
    asm("mov.b64 {%0, %1}, %2;" : "=f"(lo), "=f"(hi) : "l"(v));
}
__device__ __forceinline__ void fma2(ull& d, ull a, ull b) {   // d += a*b
    asm("fma.rn.f32x2 %0, %1, %2, %0;" : "+l"(d) : "l"(a), "l"(b));
}
__device__ __forceinline__ void fma2h(ull& d, ull a, ull c) {  // d = d*a + c
    asm("fma.rn.f32x2 %0, %0, %1, %2;" : "+l"(d) : "l"(a), "l"(c));
}
__device__ __forceinline__ ull add2(ull a, ull b) {
    ull r; asm("add.rn.f32x2 %0, %1, %2;" : "=l"(r) : "l"(a), "l"(b)); return r;
}
__device__ __forceinline__ ull mul2(ull a, ull b) {
    ull r; asm("mul.rn.f32x2 %0, %1, %2;" : "=l"(r) : "l"(a), "l"(b)); return r;
}
__device__ __forceinline__ ull dup(float f) { return pk(f, f); }
__device__ __forceinline__ ull swap32(ull v) { return (v >> 32) | (v << 32); }

// Packed XLA EmitFastTanh on an accumulator pair + packed bias.
// Per-lane op sequence identical to the verified scalar replica.
// DO NOT CHANGE the op sequence (bit-exactness vs XLA verified).
__device__ __forceinline__ ull xla_tanh2(ull acc, ull bias2) {
    ull s = add2(acc, bias2);
    float s0, s1; upk(s, s0, s1);
    float xc0 = fminf(fmaxf(s0, -9.0f), 9.0f);
    float xc1 = fminf(fmaxf(s1, -9.0f), 9.0f);
    ull xc = pk(xc0, xc1);
    ull x2 = mul2(xc, xc);
    ull p = dup(-2.76076847742355e-16f);
    fma2h(p, x2, dup( 2.00018790482477e-13f));
    fma2h(p, x2, dup(-8.60467152213735e-11f));
    fma2h(p, x2, dup( 5.12229709037114e-08f));
    fma2h(p, x2, dup( 1.48572235717979e-05f));
    fma2h(p, x2, dup( 6.37261928875436e-04f));
    fma2h(p, x2, dup( 4.89352455891786e-03f));
    ull num = mul2(xc, p);
    ull q = dup(1.19825839466702e-06f);
    fma2h(q, x2, dup(1.18534705686654e-04f));
    fma2h(q, x2, dup(2.26843463243900e-03f));
    fma2h(q, x2, dup(4.89352518554385e-03f));
    float n0, n1, q0, q1;
    upk(num, n0, n1); upk(q, q0, q1);
    float r0 = __fdiv_rn(n0, q0);
    float r1 = __fdiv_rn(n1, q1);
    float t0 = (fabsf(s0) < 0.0004f) ? s0 : r0;
    float t1 = (fabsf(s1) < 0.0004f) ? s1 : r1;
    return pk(t0, t1);
}

__global__ void copy_k(const float4* __restrict__ in, float4* __restrict__ out) {
    int i = blockIdx.x * blockDim.x + threadIdx.x;
    out[i] = in[i];
}

// Task decode (phases 1/2), 16 tasks per row: T -> rr = T>>4,
// p0 = (T>>1)&7 (pairs p0, p0+8, p0+16, p0+24), coB = (T&1)*8.
// 4pp x 8co = 32 acc pairs. Per (dy,dx,ci) iter: 4 act LDS.64 (32B) +
// 2 weight float4 (32B) per 32 FMA2 = 2 B/FMA2 through L1tex.
// 32 independent FMA chains per iter -> self-covering ILP per warp.

// conv1 task: chain (dy,dx)
__device__ __forceinline__ void conv1_task(ull* su, int T) {
    int rr = T >> 4;
    int p0 = (T >> 1) & 7;
    int coB = (T & 1) << 3;
    const float* wsf = (const float*)(su + WS0);
    ull acc[32];
    #pragma unroll
    for (int i = 0; i < 32; i++) acc[i] = 0ull;
    #pragma unroll
    for (int dy = 0; dy < 3; dy++) {
        const ull* rp = su + SZU + (rr + dy) * PW + 1;
        #pragma unroll
        for (int dx = 0; dx < 3; dx++) {
            const float* wq = wsf + (dy * 3 + dx) * 16 + coB;
            float4 wa = *(const float4*)(wq);
            float4 wb = *(const float4*)(wq + 4);
            ull w[8];
            w[0] = dup(wa.x); w[1] = dup(wa.y); w[2] = dup(wa.z); w[3] = dup(wa.w);
            w[4] = dup(wb.x); w[5] = dup(wb.y); w[6] = dup(wb.z); w[7] = dup(wb.w);
            #pragma unroll
            for (int k = 0; k < 4; k++) {
                ull q = rp[p0 + 8 * k + dx - 1];
                #pragma unroll
                for (int j = 0; j < 8; j++)
                    fma2(acc[k * 8 + j], w[j], q);
            }
        }
    }
    #pragma unroll
    for (int j = 0; j < 8; j++) {
        int co = coB + j;
        ull b2v = su[BFU + co];
        ull* op = su + S1U + (co * R1 + rr) * PW + 1;
        #pragma unroll
        for (int k = 0; k < 4; k++) {
            ull r = xla_tanh2(acc[k * 8 + j], b2v);
            op[p0 + 8 * k] = r;
            if (k == 3 && p0 == 7) op[-1] = swap32(r);  // halo = swap(pair 31)
            if (k == 0 && p0 == 0) op[32] = swap32(r);  // halo = swap(pair 0)
        }
    }
}

// conv2 task: chain (dy,dx,ci), ci-loop manually pipelined (depth 1)
__device__ __forceinline__ void conv2_task(ull* su, int T) {
    int rr = T >> 4;
    int p0 = (T >> 1) & 7;
    int coB = (T & 1) << 3;
    const float* wsf = (const float*)(su + WS1);
    ull acc[32];
    #pragma unroll
    for (int i = 0; i < 32; i++) acc[i] = 0ull;
    #pragma unroll
    for (int dy = 0; dy < 3; dy++) {
        const ull* rbp = su + S1U + (rr + dy) * PW + 1;
        #pragma unroll
        for (int dx = 0; dx < 3; dx++) {
            const float* wb = wsf + (dy * 3 + dx) * 256 + coB;
            // pipeline prologue: ci = 0
            ull q0v = rbp[p0 + dx - 1];
            ull q1v = rbp[p0 + 8 + dx - 1];
            ull q2v = rbp[p0 + 16 + dx - 1];
            ull q3v = rbp[p0 + 24 + dx - 1];
            float4 wva = *(const float4*)(wb);
            float4 wvb = *(const float4*)(wb + 4);
            #pragma unroll
            for (int ci = 0; ci < 16; ci++) {
                ull n0 = q0v, n1 = q1v, n2 = q2v, n3 = q3v;
                float4 nwa = wva, nwb = wvb;
                if (ci < 15) {                      // prefetch ci+1
                    const ull* rp = rbp + (ci + 1) * (R1 * PW);
                    n0 = rp[p0 + dx - 1];
                    n1 = rp[p0 + 8 + dx - 1];
                    n2 = rp[p0 + 16 + dx - 1];
                    n3 = rp[p0 + 24 + dx - 1];
                    nwa = *(const float4*)(wb + (ci + 1) * 16);
                    nwb = *(const float4*)(wb + (ci + 1) * 16 + 4);
                }
                ull w[8];
                w[0] = dup(wva.x); w[1] = dup(wva.y); w[2] = dup(wva.z); w[3] = dup(wva.w);
                w[4] = dup(wvb.x); w[5] = dup(wvb.y); w[6] = dup(wvb.z); w[7] = dup(wvb.w);
                #pragma unroll
                for (int j = 0; j < 8; j++) {
                    fma2(acc[0  + j], w[j], q0v);
                    fma2(acc[8  + j], w[j], q1v);
                    fma2(acc[16 + j], w[j], q2v);
                    fma2(acc[24 + j], w[j], q3v);
                }
                q0v = n0; q1v = n1; q2v = n2; q3v = n3;
                wva = nwa; wvb = nwb;
            }
        }
    }
    #pragma unroll
    for (int j = 0; j < 8; j++) {
        int co = coB + j;
        ull b2v = su[BFU + 16 + co];
        ull* op = su + S2U + (co * R2 + rr) * PW + 1;
        #pragma unroll
        for (int k = 0; k < 4; k++) {
            ull r = xla_tanh2(acc[k * 8 + j], b2v);
            op[p0 + 8 * k] = r;
            if (k == 3 && p0 == 7) op[-1] = swap32(r);
            if (k == 0 && p0 == 0) op[32] = swap32(r);
        }
    }
}

// One fused layer. All conv accumulations are single fp32 FMA chains from 0
// in k = (dy, dx, ci) order (ci fastest), bias after — bit-identical to XLA.
__global__ void __launch_bounds__(THREADS, 1)
layer_kernel(float* __restrict__ x,
             const float* __restrict__ w0, const float* __restrict__ b0,
             const float* __restrict__ w1, const float* __restrict__ b1,
             const float* __restrict__ w2, const float* __restrict__ b2,
             int parity)
{
    extern __shared__ ull su[];

    const int tid   = threadIdx.x;
    const int rbase = blockIdx.x * TH;                 // even
    const int xbase = ((int)blockIdx.y) << 12;         // b*4096

    // ---- Phase 0: scalar weights (conv1/conv2), packed W2 + biases, input ----
    {
        float* ws1 = (float*)(su + WS1);
        for (int t = tid; t < 2304; t += THREADS) ws1[t] = w1[t];
    }
    if (tid < 144) {
        ((float*)(su + WS0))[tid] = w0[tid];
        float b = w2[tid];
        su[WU2 + tid] = pk(b, b);
    }
    if (tid >= 160 && tid < 176) { int i = tid - 160; float v = b0[i]; su[BFU + i] = pk(v, v); }
    if (tid >= 192 && tid < 208) { int i = tid - 192; float v = b1[i]; su[BFU + 16 + i] = pk(v, v); }
    if (tid == 224) { float v = b2[0]; su[BFU + 32] = pk(v, v); }

    // packed masked input: entry e (0..33) of row rr holds pair p = e-1:
    // ( z[gr][p&63], z[gr][(p+32)&63] ), zeroed at non-A sites.
    for (int t = tid; t < RZ * 34; t += THREADS) {
        int rr = t / 34, e = t - rr * 34, p = e - 1;
        int gr = (rbase + rr - 3) & 63;
        int c0 = p & 63, c1 = (p + 32) & 63;
        const float* row = x + xbase + (gr << 6);
        float v0 = row[c0], v1 = row[c1];
        v0 = (((gr + c0) & 1) == parity) ? v0 : 0.0f;
        v1 = (((gr + c1) & 1) == parity) ? v1 : 0.0f;
        su[SZU + rr * PW + e] = pk(v0, v1);
    }
    __syncthreads();

    // ---- Phase 1: conv1 (1 -> 16): 320 tasks (20 rows x 8 pQ x 2 coH) ----
    if (tid < 320) conv1_task(su, tid);
    __syncthreads();

    // ---- Phase 2: conv2 (16 -> 16): 288 tasks (18 rows x 8 pQ x 2 coH) ----
    if (tid < 288) conv2_task(su, tid);
    __syncthreads();

    // ---- Phase 3: conv3 (16 -> 1), chain (dy,dx,ci), bias, STE sign update ----
    // 512 tasks: 16 rows x 32 pairs; pair p0 covers columns (p0, p0+32)
    {
        int rr = tid >> 5;
        int p0 = tid & 31;
        ull acc = 0ull;
        #pragma unroll
        for (int dy = 0; dy < 3; dy++) {
            const ull* rbp = su + S2U + (rr + dy) * PW + 1;
            #pragma unroll
            for (int dx = 0; dx < 3; dx++) {
                const ull* wp = su + WU2 + (dy * 3 + dx) * 16;
                // manual 1-deep pipeline
                ull qa = rbp[p0 + dx - 1];
                ull wv = wp[0];
                #pragma unroll
                for (int ci = 0; ci < 16; ci++) {
                    ull nqa = qa, nwv = wv;
                    if (ci < 15) {
                        nqa = rbp[(ci + 1) * (R2 * PW) + p0 + dx - 1];
                        nwv = wp[ci + 1];
                    }
                    fma2(acc, wv, qa);
                    qa = nqa; wv = nwv;
                }
            }
        }
        float bb, dummy;
        upk(su[BFU + 32], bb, dummy);
        float u0, u1;
        upk(acc, u0, u1);
        float l0 = __fadd_rn(u0, bb);
        float l1 = __fadd_rn(u1, bb);
        int gr = rbase + rr;
        // columns p0 and p0+32 share parity -> uniform condition per thread
        if (((gr + p0) & 1) != parity) {
            float* row = x + xbase + (gr << 6);
            float s0 = (l0 > 0.0f) ? 1.0f : ((l0 < 0.0f) ? -1.0f : 0.0f);
            float s1v = (l1 > 0.0f) ? 1.0f : ((l1 < 0.0f) ? -1.0f : 0.0f);
            // STE forward exactly as XLA computes it: l + (sign(l) - l)
            float m0 = __fadd_rn(l0, __fadd_rn(s0, -l0));
            float m1 = __fadd_rn(l1, __fadd_rn(s1v, -l1));
            row[p0]      = __fmul_rn(row[p0],      m0);
            row[p0 + 32] = __fmul_rn(row[p0 + 32], m1);
        }
    }
}

extern "C" void kernel_launch(void* const* d_in, const int* in_sizes, int n_in,
                              void* d_out, int out_size)
{
    const float* z  = (const float*)d_in[0];
    const float* W0 = (const float*)d_in[1];
    const float* b0 = (const float*)d_in[2];
    const float* W1 = (const float*)d_in[3];
    const float* b1 = (const float*)d_in[4];
    const float* W2 = (const float*)d_in[5];
    const float* b2 = (const float*)d_in[6];
    float* x = (float*)d_out;

    cudaFuncSetAttribute(layer_kernel, cudaFuncAttributeMaxDynamicSharedMemorySize,
                         (int)SMEM_BYTES);

    // reset working state each replay: x <- z
    copy_k<<<(Bg * Lg * Lg) / (4 * 256), 256>>>((const float4*)z, (float4*)x);

    for (int i = 0; i < 4; i++) {
        layer_kernel<<<dim3(NTILES, Bg), THREADS, SMEM_BYTES>>>(
            x,
            W0 + i * 144, b0 + i * 16,
            W1 + i * 2304, b1 + i * 16,
            W2 + i * 144, b2 + i,
            i & 1);
    }
}

// round 16
// speedup vs baseline: 1.1200x; 1.1200x over previous
#include <cuda_runtime.h>

typedef unsigned long long ull;

#define Lg 64
#define Bg 1024
#define TH 16
#define NTILES (Lg/TH)          // 4
#define THREADS 640
#define R1 (TH+4)               // 20 conv1 output rows (halo 2)
#define R2 (TH+2)               // 18 conv2 output rows (halo 1)
#define RZ (TH+6)               // 22 input rows (halo 3)
#define PW 36                   // row stride in ull: 72 words = 8 banks ->
                                // 4-rows-per-warp act loads hit each bank 2x (2 wf)

// ---- shared memory layout (ull units) — activations only; weights in constant ----
#define S1U 0                               // 16*20*36 = 11520
#define S2U (S1U + 16*R1*PW)                // 11520 (+16*18*36 = 10368)
#define SZU (S2U + 16*R2*PW)                // 21888 (+22*36 = 792)
#define U_TOTAL (SZU + RZ*PW)               // 22680
#define SMEM_BYTES ((size_t)U_TOTAL * 8)    // 181440 B

// ---- all weights/biases in constant memory (warp-uniform access -> LDC, off L1tex) ----
__constant__ float cW0[4 * 144];
__constant__ float cW1[4 * 2304];
__constant__ float cW2[4 * 144];
__constant__ float cB0[4 * 16];
__constant__ float cB1[4 * 16];
__constant__ float cB2[4];

// ---- packed f32x2 helpers (sm_100+) : per-lane exact fp32 ops ----
__device__ __forceinline__ ull pk(float lo, float hi) {
    ull r; asm("mov.b64 %0, {%1, %2};" : "=l"(r) : "f"(lo), "f"(hi)); return r;
}
__device__ __forceinline__ void upk(ull v, float& lo, float& hi) {
    asm("mov.b64 {%0, %1}, %2;" : "=f"(lo), "=f"(hi) : "l"(v));
}
__device__ __forceinline__ void fma2(ull& d, ull a, ull b) {   // d += a*b
    asm("fma.rn.f32x2 %0, %1, %2, %0;" : "+l"(d) : "l"(a), "l"(b));
}
__device__ __forceinline__ void fma2h(ull& d, ull a, ull c) {  // d = d*a + c
    asm("fma.rn.f32x2 %0, %0, %1, %2;" : "+l"(d) : "l"(a), "l"(c));
}
__device__ __forceinline__ ull add2(ull a, ull b) {
    ull r; asm("add.rn.f32x2 %0, %1, %2;" : "=l"(r) : "l"(a), "l"(b)); return r;
}
__device__ __forceinline__ ull mul2(ull a, ull b) {
    ull r; asm("mul.rn.f32x2 %0, %1, %2;" : "=l"(r) : "l"(a), "l"(b)); return r;
}
__device__ __forceinline__ ull dup(float f) { return pk(f, f); }
__device__ __forceinline__ ull swap32(ull v) { return (v >> 32) | (v << 32); }

// Packed XLA EmitFastTanh on an accumulator pair + packed bias.
// Per-lane op sequence identical to the verified scalar replica.
// DO NOT CHANGE the op sequence (bit-exactness vs XLA verified).
__device__ __forceinline__ ull xla_tanh2(ull acc, ull bias2) {
    ull s = add2(acc, bias2);
    float s0, s1; upk(s, s0, s1);
    float xc0 = fminf(fmaxf(s0, -9.0f), 9.0f);
    float xc1 = fminf(fmaxf(s1, -9.0f), 9.0f);
    ull xc = pk(xc0, xc1);
    ull x2 = mul2(xc, xc);
    ull p = dup(-2.76076847742355e-16f);
    fma2h(p, x2, dup( 2.00018790482477e-13f));
    fma2h(p, x2, dup(-8.60467152213735e-11f));
    fma2h(p, x2, dup( 5.12229709037114e-08f));
    fma2h(p, x2, dup( 1.48572235717979e-05f));
    fma2h(p, x2, dup( 6.37261928875436e-04f));
    fma2h(p, x2, dup( 4.89352455891786e-03f));
    ull num = mul2(xc, p);
    ull q = dup(1.19825839466702e-06f);
    fma2h(q, x2, dup(1.18534705686654e-04f));
    fma2h(q, x2, dup(2.26843463243900e-03f));
    fma2h(q, x2, dup(4.89352518554385e-03f));
    float n0, n1, q0, q1;
    upk(num, n0, n1); upk(q, q0, q1);
    float r0 = __fdiv_rn(n0, q0);
    float r1 = __fdiv_rn(n1, q1);
    float t0 = (fabsf(s0) < 0.0004f) ? s0 : r0;
    float t1 = (fabsf(s1) < 0.0004f) ? s1 : r1;
    return pk(t0, t1);
}

__global__ void copy_k(const float4* __restrict__ in, float4* __restrict__ out) {
    int i = blockIdx.x * blockDim.x + threadIdx.x;
    out[i] = in[i];
}

// Warp-uniform-co task decode: warp wid -> coB = (wid&3)*4 (UNIFORM),
// row block = (wid>>2)*4; lane -> row = block + (lane>>3), p0 = lane&7.
// Weights/biases: warp-uniform constant loads (no L1tex wavefronts).
// Acts: 4 rows x 8 p0 per warp; PW=36 -> every bank exactly 2x = 2 wf/load.

// conv1 task (rows 0..19 via 20 warps), chain (dy,dx)
__device__ __forceinline__ void conv1_task(ull* su, const float* w0c, const float* b0c,
                                           int wid, int lane) {
    int rr = ((wid >> 2) << 2) + (lane >> 3);
    int p0 = lane & 7;
    int coB = (wid & 3) << 2;
    ull acc[16];
    #pragma unroll
    for (int i = 0; i < 16; i++) acc[i] = 0ull;
    #pragma unroll
    for (int dy = 0; dy < 3; dy++) {
        const ull* rp = su + SZU + (rr + dy) * PW + 1;
        #pragma unroll
        for (int dx = 0; dx < 3; dx++) {
            float4 wv = *(const float4*)(w0c + (dy * 3 + dx) * 16 + coB);
            ull w0p = dup(wv.x), w1p = dup(wv.y), w2p = dup(wv.z), w3p = dup(wv.w);
            #pragma unroll
            for (int k = 0; k < 4; k++) {
                ull q = rp[p0 + 8 * k + dx - 1];
                fma2(acc[4*k + 0], w0p, q);
                fma2(acc[4*k + 1], w1p, q);
                fma2(acc[4*k + 2], w2p, q);
                fma2(acc[4*k + 3], w3p, q);
            }
        }
    }
    #pragma unroll
    for (int j = 0; j < 4; j++) {
        int co = coB + j;
        ull b2v = dup(b0c[co]);
        ull* op = su + S1U + (co * R1 + rr) * PW + 1;
        #pragma unroll
        for (int k = 0; k < 4; k++) {
            ull r = xla_tanh2(acc[4*k + j], b2v);
            op[p0 + 8 * k] = r;
            if (k == 3 && p0 == 7) op[-1] = swap32(r);  // halo = swap(pair 31)
            if (k == 0 && p0 == 0) op[32] = swap32(r);  // halo = swap(pair 0)
        }
    }
}

// conv2 main (rows 0..15, warps 0..15): chain (dy,dx,ci), pipelined depth 1
__device__ __forceinline__ void conv2_main(ull* su, const float* w1c, const float* b1c,
                                           int wid, int lane) {
    int rr = ((wid >> 2) << 2) + (lane >> 3);
    int p0 = lane & 7;
    int coB = (wid & 3) << 2;
    ull acc[16];
    #pragma unroll
    for (int i = 0; i < 16; i++) acc[i] = 0ull;
    #pragma unroll
    for (int dy = 0; dy < 3; dy++) {
        const ull* rbp = su + S1U + (rr + dy) * PW + 1;
        #pragma unroll
        for (int dx = 0; dx < 3; dx++) {
            const float* wb = w1c + (dy * 3 + dx) * 256 + coB;
            ull q0v = rbp[p0 + dx - 1];
            ull q1v = rbp[p0 + 8 + dx - 1];
            ull q2v = rbp[p0 + 16 + dx - 1];
            ull q3v = rbp[p0 + 24 + dx - 1];
            float4 wv = *(const float4*)(wb);
            #pragma unroll
            for (int ci = 0; ci < 16; ci++) {
                ull n0 = q0v, n1 = q1v, n2 = q2v, n3 = q3v;
                float4 nwv = wv;
                if (ci < 15) {                      // prefetch ci+1
                    const ull* rp = rbp + (ci + 1) * (R1 * PW);
                    n0 = rp[p0 + dx - 1];
                    n1 = rp[p0 + 8 + dx - 1];
                    n2 = rp[p0 + 16 + dx - 1];
                    n3 = rp[p0 + 24 + dx - 1];
                    nwv = *(const float4*)(wb + (ci + 1) * 16);
                }
                ull w0p = dup(wv.x), w1p = dup(wv.y), w2p = dup(wv.z), w3p = dup(wv.w);
                fma2(acc[0],  w0p, q0v); fma2(acc[1],  w1p, q0v);
                fma2(acc[2],  w2p, q0v); fma2(acc[3],  w3p, q0v);
                fma2(acc[4],  w0p, q1v); fma2(acc[5],  w1p, q1v);
                fma2(acc[6],  w2p, q1v); fma2(acc[7],  w3p, q1v);
                fma2(acc[8],  w0p, q2v); fma2(acc[9],  w1p, q2v);
                fma2(acc[10], w2p, q2v); fma2(acc[11], w3p, q2v);
                fma2(acc[12], w0p, q3v); fma2(acc[13], w1p, q3v);
                fma2(acc[14], w2p, q3v); fma2(acc[15], w3p, q3v);
                q0v = n0; q1v = n1; q2v = n2; q3v = n3;
                wv = nwv;
            }
        }
    }
    #pragma unroll
    for (int j = 0; j < 4; j++) {
        int co = coB + j;
        ull b2v = dup(b1c[co]);
        ull* op = su + S2U + (co * R2 + rr) * PW + 1;
        #pragma unroll
        for (int k = 0; k < 4; k++) {
            ull r = xla_tanh2(acc[4*k + j], b2v);
            op[p0 + 8 * k] = r;
            if (k == 3 && p0 == 7) op[-1] = swap32(r);
            if (k == 0 && p0 == 0) op[32] = swap32(r);
        }
    }
}

// conv2 tail (rows 16..17, warps 16..19): 2pp x 4co, coQ warp-uniform
__device__ __forceinline__ void conv2_tail(ull* su, const float* w1c, const float* b1c,
                                           int wid, int lane) {
    int rr = 16 + (lane >> 4);
    int pg = lane & 15;                      // pairs pg, pg+16
    int coB = (wid & 3) << 2;
    ull acc[8];
    #pragma unroll
    for (int i = 0; i < 8; i++) acc[i] = 0ull;
    #pragma unroll
    for (int dy = 0; dy < 3; dy++) {
        const ull* rbp = su + S1U + (rr + dy) * PW + 1;
        #pragma unroll
        for (int dx = 0; dx < 3; dx++) {
            const float* wb = w1c + (dy * 3 + dx) * 256 + coB;
            ull q0v = rbp[pg + dx - 1];
            ull q1v = rbp[pg + 16 + dx - 1];
            float4 wv = *(const float4*)(wb);
            #pragma unroll
            for (int ci = 0; ci < 16; ci++) {
                ull n0 = q0v, n1 = q1v;
                float4 nwv = wv;
                if (ci < 15) {
                    const ull* rp = rbp + (ci + 1) * (R1 * PW);
                    n0 = rp[pg + dx - 1];
                    n1 = rp[pg + 16 + dx - 1];
                    nwv = *(const float4*)(wb + (ci + 1) * 16);
                }
                ull w0p = dup(wv.x), w1p = dup(wv.y), w2p = dup(wv.z), w3p = dup(wv.w);
                fma2(acc[0], w0p, q0v); fma2(acc[1], w1p, q0v);
                fma2(acc[2], w2p, q0v); fma2(acc[3], w3p, q0v);
                fma2(acc[4], w0p, q1v); fma2(acc[5], w1p, q1v);
                fma2(acc[6], w2p, q1v); fma2(acc[7], w3p, q1v);
                q0v = n0; q1v = n1; wv = nwv;
            }
        }
    }
    #pragma unroll
    for (int j = 0; j < 4; j++) {
        int co = coB + j;
        ull b2v = dup(b1c[co]);
        ull* op = su + S2U + (co * R2 + rr) * PW + 1;
        #pragma unroll
        for (int k = 0; k < 2; k++) {
            ull r = xla_tanh2(acc[4*k + j], b2v);
            op[pg + 16 * k] = r;
            if (k == 1 && pg == 15) op[-1] = swap32(r);  // pair 31 halo
            if (k == 0 && pg == 0)  op[32] = swap32(r);  // pair 0 halo
        }
    }
}

// One fused layer. All conv accumulations are single fp32 FMA chains from 0
// in k = (dy, dx, ci) order (ci fastest), bias after — bit-identical to XLA.
__global__ void __launch_bounds__(THREADS, 1)
layer_kernel(float* __restrict__ x, int layer, int parity)
{
    extern __shared__ ull su[];

    const int tid   = threadIdx.x;
    const int wid   = tid >> 5;
    const int lane  = tid & 31;
    const int rbase = blockIdx.x * TH;                 // even
    const int xbase = ((int)blockIdx.y) << 12;         // b*4096

    const float* w0c = cW0 + layer * 144;
    const float* w1c = cW1 + layer * 2304;
    const float* w2c = cW2 + layer * 144;
    const float* b0c = cB0 + layer * 16;
    const float* b1c = cB1 + layer * 16;

    // ---- Phase 0: packed masked input only (weights live in constant mem) ----
    // entry e (0..33) of row rr holds pair p = e-1:
    // ( z[gr][p&63], z[gr][(p+32)&63] ), zeroed at non-A sites.
    for (int t = tid; t < RZ * 34; t += THREADS) {
        int rr = t / 34, e = t - rr * 34, p = e - 1;
        int gr = (rbase + rr - 3) & 63;
        int c0 = p & 63, c1 = (p + 32) & 63;
        const float* row = x + xbase + (gr << 6);
        float v0 = row[c0], v1 = row[c1];
        v0 = (((gr + c0) & 1) == parity) ? v0 : 0.0f;
        v1 = (((gr + c1) & 1) == parity) ? v1 : 0.0f;
        su[SZU + rr * PW + e] = pk(v0, v1);
    }
    __syncthreads();

    // ---- Phase 1: conv1 (1 -> 16): 640 tasks, rows 0..19, all 20 warps ----
    conv1_task(su, w0c, b0c, wid, lane);
    __syncthreads();

    // ---- Phase 2: conv2 (16 -> 16): 16 main warps + 4 tail warps ----
    if (wid < 16) conv2_main(su, w1c, b1c, wid, lane);
    else          conv2_tail(su, w1c, b1c, wid, lane);
    __syncthreads();

    // ---- Phase 3: conv3 (16 -> 1), chain (dy,dx,ci), bias, STE sign update ----
    // 512 tasks (warps 0..15): 16 rows x 32 pairs; pair p0 = cols (p0, p0+32)
    if (wid < 16) {
        int rr = wid;
        int p0 = lane;
        ull acc = 0ull;
        #pragma unroll
        for (int dy = 0; dy < 3; dy++) {
            const ull* rbp = su + S2U + (rr + dy) * PW + 1;
            #pragma unroll
            for (int dx = 0; dx < 3; dx++) {
                const float* wp = w2c + (dy * 3 + dx) * 16;
                // manual 1-deep pipeline (weights: uniform constant loads)
                ull qa = rbp[p0 + dx - 1];
                float wv = wp[0];
                #pragma unroll
                for (int ci = 0; ci < 16; ci++) {
                    ull nqa = qa; float nwv = wv;
                    if (ci < 15) {
                        nqa = rbp[(ci + 1) * (R2 * PW) + p0 + dx - 1];
                        nwv = wp[ci + 1];
                    }
                    fma2(acc, dup(wv), qa);
                    qa = nqa; wv = nwv;
                }
            }
        }
        float bb = cB2[layer];
        float u0, u1;
        upk(acc, u0, u1);
        float l0 = __fadd_rn(u0, bb);
        float l1 = __fadd_rn(u1, bb);
        int gr = rbase + rr;
        // columns p0 and p0+32 share parity -> uniform condition per thread
        if (((gr + p0) & 1) != parity) {
            float* row = x + xbase + (gr << 6);
            float s0 = (l0 > 0.0f) ? 1.0f : ((l0 < 0.0f) ? -1.0f : 0.0f);
            float s1v = (l1 > 0.0f) ? 1.0f : ((l1 < 0.0f) ? -1.0f : 0.0f);
            // STE forward exactly as XLA computes it: l + (sign(l) - l)
            float m0 = __fadd_rn(l0, __fadd_rn(s0, -l0));
            float m1 = __fadd_rn(l1, __fadd_rn(s1v, -l1));
            row[p0]      = __fmul_rn(row[p0],      m0);
            row[p0 + 32] = __fmul_rn(row[p0 + 32], m1);
        }
    }
}

extern "C" void kernel_launch(void* const* d_in, const int* in_sizes, int n_in,
                              void* d_out, int out_size)
{
    const float* z  = (const float*)d_in[0];
    const float* W0 = (const float*)d_in[1];
    const float* b0 = (const float*)d_in[2];
    const float* W1 = (const float*)d_in[3];
    const float* b1 = (const float*)d_in[4];
    const float* W2 = (const float*)d_in[5];
    const float* b2 = (const float*)d_in[6];
    float* x = (float*)d_out;

    cudaFuncSetAttribute(layer_kernel, cudaFuncAttributeMaxDynamicSharedMemorySize,
                         (int)SMEM_BYTES);

    // stage weights/biases into constant memory (D2D async, graph-capturable)
    cudaMemcpyToSymbolAsync(cW0, W0, 4 * 144 * sizeof(float),  0, cudaMemcpyDeviceToDevice, 0);
    cudaMemcpyToSymbolAsync(cW1, W1, 4 * 2304 * sizeof(float), 0, cudaMemcpyDeviceToDevice, 0);
    cudaMemcpyToSymbolAsync(cW2, W2, 4 * 144 * sizeof(float),  0, cudaMemcpyDeviceToDevice, 0);
    cudaMemcpyToSymbolAsync(cB0, b0, 4 * 16 * sizeof(float),   0, cudaMemcpyDeviceToDevice, 0);
    cudaMemcpyToSymbolAsync(cB1, b1, 4 * 16 * sizeof(float),   0, cudaMemcpyDeviceToDevice, 0);
    cudaMemcpyToSymbolAsync(cB2, b2, 4 * sizeof(float),        0, cudaMemcpyDeviceToDevice, 0);

    // reset working state each replay: x <- z
    copy_k<<<(Bg * Lg * Lg) / (4 * 256), 256>>>((const float4*)z, (float4*)x);

    for (int i = 0; i < 4; i++) {
        layer_kernel<<<dim3(NTILES, Bg), THREADS, SMEM_BYTES>>>(x, i, i & 1);
    }
}

// round 17
// speedup vs baseline: 1.3826x; 1.2345x over previous
#include <cuda_runtime.h>

typedef unsigned long long ull;

#define Lg 64
#define Bg 1024
#define TH 16
#define NTILES (Lg/TH)          // 4
#define THREADS 640
#define R1 (TH+4)               // 20 conv1 output rows (halo 2)
#define R2 (TH+2)               // 18 conv2 output rows (halo 1)
#define RZ (TH+6)               // 22 input rows (halo 3)
#define PW 34                   // pairs per row: p = -1..32 (wrapped halo)

// ---- shared memory layout (ull units) ----
#define S1U 0                               // 16*20*34 = 10880
#define S2U (S1U + 16*R1*PW)                // 10880 (+9792)
#define SZU (S2U + 16*R2*PW)                // 20672 (+748)
#define WS1 (SZU + RZ*PW)                   // 21420: W1 SCALAR floats (1152 ull)
#define WS0 (WS1 + 1152)                    // 22572: W0 scalar (72 ull)
#define WU2 (WS0 + 72)                      // 22644: W2 packed pairs (144 ull)
#define BFU (WU2 + 144)                     // 22788: packed biases (33 ull)
#define U_TOTAL (BFU + 33)                  // 22821
#define SMEM_BYTES ((size_t)U_TOTAL * 8)    // 182568 B

// ---- packed f32x2 helpers (sm_100+) : per-lane exact fp32 ops ----
__device__ __forceinline__ ull pk(float lo, float hi) {
    ull r; asm("mov.b64 %0, {%1, %2};" : "=l"(r) : "f"(lo), "f"(hi)); return r;
}
__device__ __forceinline__ void upk(ull v, float& lo, float& hi) {
    asm("mov.b64 {%0, %1}, %2;" : "=f"(lo), "=f"(hi) : "l"(v));
}
__device__ __forceinline__ void fma2(ull& d, ull a, ull b) {   // d += a*b
    asm("fma.rn.f32x2 %0, %1, %2, %0;" : "+l"(d) : "l"(a), "l"(b));
}
__device__ __forceinline__ void fma2h(ull& d, ull a, ull c) {  // d = d*a + c
    asm("fma.rn.f32x2 %0, %0, %1, %2;" : "+l"(d) : "l"(a), "l"(c));
}
__device__ __forceinline__ ull add2(ull a, ull b) {
    ull r; asm("add.rn.f32x2 %0, %1, %2;" : "=l"(r) : "l"(a), "l"(b)); return r;
}
__device__ __forceinline__ ull mul2(ull a, ull b) {
    ull r; asm("mul.rn.f32x2 %0, %1, %2;" : "=l"(r) : "l"(a), "l"(b)); return r;
}
__device__ __forceinline__ ull dup(float f) { return pk(f, f); }
__device__ __forceinline__ ull swap32(ull v) { return (v >> 32) | (v << 32); }

// Packed XLA EmitFastTanh on an accumulator pair + packed bias.
// Per-lane op sequence identical to the verified scalar replica.
// DO NOT CHANGE the op sequence (bit-exactness vs XLA verified).
__device__ __forceinline__ ull xla_tanh2(ull acc, ull bias2) {
    ull s = add2(acc, bias2);
    float s0, s1; upk(s, s0, s1);
    float xc0 = fminf(fmaxf(s0, -9.0f), 9.0f);
    float xc1 = fminf(fmaxf(s1, -9.0f), 9.0f);
    ull xc = pk(xc0, xc1);
    ull x2 = mul2(xc, xc);
    ull p = dup(-2.76076847742355e-16f);
    fma2h(p, x2, dup( 2.00018790482477e-13f));
    fma2h(p, x2, dup(-8.60467152213735e-11f));
    fma2h(p, x2, dup( 5.12229709037114e-08f));
    fma2h(p, x2, dup( 1.48572235717979e-05f));
    fma2h(p, x2, dup( 6.37261928875436e-04f));
    fma2h(p, x2, dup( 4.89352455891786e-03f));
    ull num = mul2(xc, p);
    ull q = dup(1.19825839466702e-06f);
    fma2h(q, x2, dup(1.18534705686654e-04f));
    fma2h(q, x2, dup(2.26843463243900e-03f));
    fma2h(q, x2, dup(4.89352518554385e-03f));
    float n0, n1, q0, q1;
    upk(num, n0, n1); upk(q, q0, q1);
    float r0 = __fdiv_rn(n0, q0);
    float r1 = __fdiv_rn(n1, q1);
    float t0 = (fabsf(s0) < 0.0004f) ? s0 : r0;
    float t1 = (fabsf(s1) < 0.0004f) ? s1 : r1;
    return pk(t0, t1);
}

__global__ void copy_k(const float4* __restrict__ in, float4* __restrict__ out) {
    int i = blockIdx.x * blockDim.x + threadIdx.x;
    out[i] = in[i];
}

// Task decode (full grain): T -> rr = T>>5 (warp-uniform),
// p0 = (T>>2)&7 (pairs p0, p0+8, p0+16, p0+24), coB = (T&3)*4.
// 4pp x 4co = 16 acc pairs. Weights loaded as SCALAR float4 (16B for 4 co)
// and duplicated in-register.

// conv1 task: chain (dy,dx)
__device__ __forceinline__ void conv1_task(ull* su, int T) {
    int rr = T >> 5;
    int p0 = (T >> 2) & 7;
    int coB = (T & 3) << 2;
    const float* wsf = (const float*)(su + WS0);
    ull acc[16];
    #pragma unroll
    for (int i = 0; i < 16; i++) acc[i] = 0ull;
    #pragma unroll
    for (int dy = 0; dy < 3; dy++) {
        const ull* rp = su + SZU + (rr + dy) * PW + 1;
        #pragma unroll
        for (int dx = 0; dx < 3; dx++) {
            float4 wv = *(const float4*)(wsf + (dy * 3 + dx) * 16 + coB);
            ull w0p = dup(wv.x), w1p = dup(wv.y), w2p = dup(wv.z), w3p = dup(wv.w);
            #pragma unroll
            for (int k = 0; k < 4; k++) {
                ull q = rp[p0 + 8 * k + dx - 1];
                fma2(acc[4*k + 0], w0p, q);
                fma2(acc[4*k + 1], w1p, q);
                fma2(acc[4*k + 2], w2p, q);
                fma2(acc[4*k + 3], w3p, q);
            }
        }
    }
    #pragma unroll
    for (int j = 0; j < 4; j++) {
        int co = coB + j;
        ull b2v = su[BFU + co];
        ull* op = su + S1U + (co * R1 + rr) * PW + 1;
        #pragma unroll
        for (int k = 0; k < 4; k++) {
            ull r = xla_tanh2(acc[4*k + j], b2v);
            op[p0 + 8 * k] = r;
            if (k == 3 && p0 == 7) op[-1] = swap32(r);  // halo = swap(pair 31)
            if (k == 0 && p0 == 0) op[32] = swap32(r);  // halo = swap(pair 0)
        }
    }
}

// conv2 main task (rows 0..15): chain (dy,dx,ci), ci-loop pipelined (depth 1)
__device__ __forceinline__ void conv2_task(ull* su, int T) {
    int rr = T >> 5;
    int p0 = (T >> 2) & 7;
    int coB = (T & 3) << 2;
    const float* wsf = (const float*)(su + WS1);
    ull acc[16];
    #pragma unroll
    for (int i = 0; i < 16; i++) acc[i] = 0ull;
    #pragma unroll
    for (int dy = 0; dy < 3; dy++) {
        const ull* rbp = su + S1U + (rr + dy) * PW + 1;
        #pragma unroll
        for (int dx = 0; dx < 3; dx++) {
            const float* wb = wsf + (dy * 3 + dx) * 256 + coB;
            // pipeline prologue: ci = 0
            ull q0v = rbp[p0 + dx - 1];
            ull q1v = rbp[p0 + 8 + dx - 1];
            ull q2v = rbp[p0 + 16 + dx - 1];
            ull q3v = rbp[p0 + 24 + dx - 1];
            float4 wv = *(const float4*)(wb);
            #pragma unroll
            for (int ci = 0; ci < 16; ci++) {
                ull n0 = q0v, n1 = q1v, n2 = q2v, n3 = q3v;
                float4 nwv = wv;
                if (ci < 15) {                      // prefetch ci+1
                    const ull* rp = rbp + (ci + 1) * (R1 * PW);
                    n0 = rp[p0 + dx - 1];
                    n1 = rp[p0 + 8 + dx - 1];
                    n2 = rp[p0 + 16 + dx - 1];
                    n3 = rp[p0 + 24 + dx - 1];
                    nwv = *(const float4*)(wb + (ci + 1) * 16);
                }
                ull w0p = dup(wv.x), w1p = dup(wv.y), w2p = dup(wv.z), w3p = dup(wv.w);
                fma2(acc[0],  w0p, q0v); fma2(acc[1],  w1p, q0v);
                fma2(acc[2],  w2p, q0v); fma2(acc[3],  w3p, q0v);
                fma2(acc[4],  w0p, q1v); fma2(acc[5],  w1p, q1v);
                fma2(acc[6],  w2p, q1v); fma2(acc[7],  w3p, q1v);
                fma2(acc[8],  w0p, q2v); fma2(acc[9],  w1p, q2v);
                fma2(acc[10], w2p, q2v); fma2(acc[11], w3p, q2v);
                fma2(acc[12], w0p, q3v); fma2(acc[13], w1p, q3v);
                fma2(acc[14], w2p, q3v); fma2(acc[15], w3p, q3v);
                q0v = n0; q1v = n1; q2v = n2; q3v = n3;
                wv = nwv;
            }
        }
    }
    #pragma unroll
    for (int j = 0; j < 4; j++) {
        int co = coB + j;
        ull b2v = su[BFU + 16 + co];
        ull* op = su + S2U + (co * R2 + rr) * PW + 1;
        #pragma unroll
        for (int k = 0; k < 4; k++) {
            ull r = xla_tanh2(acc[4*k + j], b2v);
            op[p0 + 8 * k] = r;
            if (k == 3 && p0 == 7) op[-1] = swap32(r);
            if (k == 0 && p0 == 0) op[32] = swap32(r);
        }
    }
}

// conv2 tail task (rows 16..17), HALF grain 2pp x 4co (8 accs):
// t in [0,128): rr = 16 + (t>>6), p0 = (t>>2)&15 (pairs p0, p0+16), coB = (t&3)*4.
// One tail warp per SMSP -> balanced 4 full + 0.5 full per SMSP.
__device__ __forceinline__ void conv2_tail(ull* su, int t) {
    int rr = 16 + (t >> 6);
    int p0 = (t >> 2) & 15;
    int coB = (t & 3) << 2;
    const float* wsf = (const float*)(su + WS1);
    ull acc[8];
    #pragma unroll
    for (int i = 0; i < 8; i++) acc[i] = 0ull;
    #pragma unroll
    for (int dy = 0; dy < 3; dy++) {
        const ull* rbp = su + S1U + (rr + dy) * PW + 1;
        #pragma unroll
        for (int dx = 0; dx < 3; dx++) {
            const float* wb = wsf + (dy * 3 + dx) * 256 + coB;
            ull q0v = rbp[p0 + dx - 1];
            ull q1v = rbp[p0 + 16 + dx - 1];
            float4 wv = *(const float4*)(wb);
            #pragma unroll
            for (int ci = 0; ci < 16; ci++) {
                ull n0 = q0v, n1 = q1v;
                float4 nwv = wv;
                if (ci < 15) {                      // prefetch ci+1
                    const ull* rp = rbp + (ci + 1) * (R1 * PW);
                    n0 = rp[p0 + dx - 1];
                    n1 = rp[p0 + 16 + dx - 1];
                    nwv = *(const float4*)(wb + (ci + 1) * 16);
                }
                ull w0p = dup(wv.x), w1p = dup(wv.y), w2p = dup(wv.z), w3p = dup(wv.w);
                fma2(acc[0], w0p, q0v); fma2(acc[1], w1p, q0v);
                fma2(acc[2], w2p, q0v); fma2(acc[3], w3p, q0v);
                fma2(acc[4], w0p, q1v); fma2(acc[5], w1p, q1v);
                fma2(acc[6], w2p, q1v); fma2(acc[7], w3p, q1v);
                q0v = n0; q1v = n1;
                wv = nwv;
            }
        }
    }
    #pragma unroll
    for (int j = 0; j < 4; j++) {
        int co = coB + j;
        ull b2v = su[BFU + 16 + co];
        ull* op = su + S2U + (co * R2 + rr) * PW + 1;
        #pragma unroll
        for (int k = 0; k < 2; k++) {
            ull r = xla_tanh2(acc[4*k + j], b2v);
            op[p0 + 16 * k] = r;
            if (k == 1 && p0 == 15) op[-1] = swap32(r);  // halo = swap(pair 31)
            if (k == 0 && p0 == 0)  op[32] = swap32(r);  // halo = swap(pair 0)
        }
    }
}

// One fused layer. All conv accumulations are single fp32 FMA chains from 0
// in k = (dy, dx, ci) order (ci fastest), bias after — bit-identical to XLA.
__global__ void __launch_bounds__(THREADS, 1)
layer_kernel(float* __restrict__ x,
             const float* __restrict__ w0, const float* __restrict__ b0,
             const float* __restrict__ w1, const float* __restrict__ b1,
             const float* __restrict__ w2, const float* __restrict__ b2,
             int parity)
{
    extern __shared__ ull su[];

    const int tid   = threadIdx.x;
    const int rbase = blockIdx.x * TH;                 // even
    const int xbase = ((int)blockIdx.y) << 12;         // b*4096

    // ---- Phase 0: scalar weights (conv1/conv2), packed W2 + biases, input ----
    {
        float* ws1 = (float*)(su + WS1);
        for (int t = tid; t < 2304; t += THREADS) ws1[t] = w1[t];
    }
    if (tid < 144) {
        ((float*)(su + WS0))[tid] = w0[tid];
        float b = w2[tid];
        su[WU2 + tid] = pk(b, b);
    }
    if (tid >= 160 && tid < 176) { int i = tid - 160; float v = b0[i]; su[BFU + i] = pk(v, v); }
    if (tid >= 192 && tid < 208) { int i = tid - 192; float v = b1[i]; su[BFU + 16 + i] = pk(v, v); }
    if (tid == 224) { float v = b2[0]; su[BFU + 32] = pk(v, v); }

    // packed masked input: entry e of row rr holds pair p = e-1:
    // ( z[gr][p&63], z[gr][(p+32)&63] ), zeroed at non-A sites.
    for (int t = tid; t < RZ * PW; t += THREADS) {
        int rr = t / PW, e = t - rr * PW, p = e - 1;
        int gr = (rbase + rr - 3) & 63;
        int c0 = p & 63, c1 = (p + 32) & 63;
        const float* row = x + xbase + (gr << 6);
        float v0 = row[c0], v1 = row[c1];
        v0 = (((gr + c0) & 1) == parity) ? v0 : 0.0f;
        v1 = (((gr + c1) & 1) == parity) ? v1 : 0.0f;
        su[SZU + t] = pk(v0, v1);
    }
    __syncthreads();

    // ---- Phase 1: conv1 (1 -> 16): EXACTLY 640 tasks (20 rows x 8 pQ x 4 coQ) ----
    conv1_task(su, tid);
    __syncthreads();

    // ---- Phase 2: conv2 (16 -> 16), SMSP-balanced: ----
    // rows 0..15 full grain (512 tasks, warps 0..15 = 4/SMSP) +
    // rows 16..17 half grain (128 tasks, warps 16..19 = 1/SMSP)
    if (tid < 512) conv2_task(su, tid);
    else           conv2_tail(su, tid - 512);
    __syncthreads();

    // ---- Phase 3: conv3 (16 -> 1), chain (dy,dx,ci), bias, STE sign update ----
    // 512 tasks: 16 rows x 32 pairs; pair p0 covers columns (p0, p0+32)
    if (tid < TH * 32) {
        int rr = tid >> 5;
        int p0 = tid & 31;
        ull acc = 0ull;
        #pragma unroll
        for (int dy = 0; dy < 3; dy++) {
            const ull* rbp = su + S2U + (rr + dy) * PW + 1;
            #pragma unroll
            for (int dx = 0; dx < 3; dx++) {
                const ull* wp = su + WU2 + (dy * 3 + dx) * 16;
                // manual 1-deep pipeline
                ull qa = rbp[p0 + dx - 1];
                ull wv = wp[0];
                #pragma unroll
                for (int ci = 0; ci < 16; ci++) {
                    ull nqa = qa, nwv = wv;
                    if (ci < 15) {
                        nqa = rbp[(ci + 1) * (R2 * PW) + p0 + dx - 1];
                        nwv = wp[ci + 1];
                    }
                    fma2(acc, wv, qa);
                    qa = nqa; wv = nwv;
                }
            }
        }
        float bb, dummy;
        upk(su[BFU + 32], bb, dummy);
        float u0, u1;
        upk(acc, u0, u1);
        float l0 = __fadd_rn(u0, bb);
        float l1 = __fadd_rn(u1, bb);
        int gr = rbase + rr;
        // columns p0 and p0+32 share parity -> uniform condition per thread
        if (((gr + p0) & 1) != parity) {
            float* row = x + xbase + (gr << 6);
            float s0 = (l0 > 0.0f) ? 1.0f : ((l0 < 0.0f) ? -1.0f : 0.0f);
            float s1v = (l1 > 0.0f) ? 1.0f : ((l1 < 0.0f) ? -1.0f : 0.0f);
            // STE forward exactly as XLA computes it: l + (sign(l) - l)
            float m0 = __fadd_rn(l0, __fadd_rn(s0, -l0));
            float m1 = __fadd_rn(l1, __fadd_rn(s1v, -l1));
            row[p0]      = __fmul_rn(row[p0],      m0);
            row[p0 + 32] = __fmul_rn(row[p0 + 32], m1);
        }
    }
}

extern "C" void kernel_launch(void* const* d_in, const int* in_sizes, int n_in,
                              void* d_out, int out_size)
{
    const float* z  = (const float*)d_in[0];
    const float* W0 = (const float*)d_in[1];
    const float* b0 = (const float*)d_in[2];
    const float* W1 = (const float*)d_in[3];
    const float* b1 = (const float*)d_in[4];
    const float* W2 = (const float*)d_in[5];
    const float* b2 = (const float*)d_in[6];
    float* x = (float*)d_out;

    cudaFuncSetAttribute(layer_kernel, cudaFuncAttributeMaxDynamicSharedMemorySize,
                         (int)SMEM_BYTES);

    // reset working state each replay: x <- z
    copy_k<<<(Bg * Lg * Lg) / (4 * 256), 256>>>((const float4*)z, (float4*)x);

    for (int i = 0; i < 4; i++) {
        layer_kernel<<<dim3(NTILES, Bg), THREADS, SMEM_BYTES>>>(
            x,
            W0 + i * 144, b0 + i * 16,
            W1 + i * 2304, b1 + i * 16,
            W2 + i * 144, b2 + i,
            i & 1);
    }
}